// round 5
// baseline (speedup 1.0000x reference)
#include <cuda_runtime.h>
#include <cstdint>

// MI over 8192x8192 fp32 contingency table, single-pass decomposition:
//   MI = sum_{c>0} c*log2(c) - sum_i mx_i*log2(mx_i) - sum_j my_j*log2(my_j)
// Round 5: cp.async (LDGSTS) 6-stage SMEM pipeline. Pipeline depth comes from
// SMEM (192KB in flight/SM), not registers, so loads stay in flight through
// the whole consume phase. Each thread consumes only its own loaded slots ->
// warp-synchronous, no __syncthreads in the hot loop. Fused last-block
// finalization kept from round 4.

#define NROWS 8192
#define MCOLS 8192
#define NTHREADS 1024
#define NBLOCKS 148
#define STAGES 6
#define ROW_F4 2048                    // float4 per row
#define STAGE_BYTES (ROW_F4 * 16)      // 32KB
#define SMEM_BYTES (STAGES * STAGE_BYTES)

__device__ float        g_rowsum[NROWS];
__device__ float        g_colsum[MCOLS];
__device__ double       g_clogc;
__device__ unsigned int g_done;

__global__ void mi_zero_kernel() {
    int t = blockIdx.x * blockDim.x + threadIdx.x;
    int stride = gridDim.x * blockDim.x;
    for (int i = t; i < NROWS; i += stride) g_rowsum[i] = 0.0f;
    for (int i = t; i < MCOLS; i += stride) g_colsum[i] = 0.0f;
    if (t == 0) { g_clogc = 0.0; g_done = 0u; }
}

// ---- cp.async helpers ----
__device__ __forceinline__ void cp_async16(uint32_t saddr, const float* gptr) {
    asm volatile("cp.async.cg.shared.global [%0], [%1], 16;"
                 :: "r"(saddr), "l"(gptr) : "memory");
}
__device__ __forceinline__ void cp_commit() {
    asm volatile("cp.async.commit_group;" ::: "memory");
}
template <int N>
__device__ __forceinline__ void cp_wait() {
    asm volatile("cp.async.wait_group %0;" :: "n"(N) : "memory");
}

// c*log2(c) masked at c>0, branchless, exact at c==0 (0 * finite = 0).
__device__ __forceinline__ void clog2c(float v, float& acc) {
    acc = __fmaf_rn(v, __log2f(fmaxf(v, 1e-30f)), acc);
}
__device__ __forceinline__ void clog4(const float4& v, float& acc) {
    clog2c(v.x, acc); clog2c(v.y, acc); clog2c(v.z, acc); clog2c(v.w, acc);
}
__device__ __forceinline__ float sum4(const float4& v) {
    return (v.x + v.y) + (v.z + v.w);
}

struct Acc {
    float ac0x, ac0y, ac0z, ac0w;   // columns 4t..4t+3
    float ac1x, ac1y, ac1z, ac1w;   // columns 4096+4t..4096+4t+3
    float cl0, cl1;
};

__global__ __launch_bounds__(NTHREADS, 1)
void mi_main_kernel(const float* __restrict__ C, float* __restrict__ out) {
    extern __shared__ float4 sbuf[];   // STAGES * ROW_F4 float4
    const int t = threadIdx.x;
    const int b = blockIdx.x;
    const uint32_t smem_base = (uint32_t)__cvta_generic_to_shared(sbuf);

    const int cnt = (NROWS - 1 - b) / NBLOCKS + 1;   // 55 or 56 rows

    Acc A = {0,0,0,0, 0,0,0,0, 0,0};

    // ---- producer lambda-equivalent: issue one row into a stage ----
    auto issue = [&](int k) {
        const int r = b + k * NBLOCKS;
        const float* g = C + (size_t)r * MCOLS + (size_t)t * 4;
        uint32_t s = smem_base + (uint32_t)(k % STAGES) * STAGE_BYTES + (uint32_t)t * 16;
        cp_async16(s, g);
        cp_async16(s + ROW_F4 / 2 * 16, g + MCOLS / 2);
        cp_commit();
    };

    // ---- consumer: process one row resident in its stage ----
    auto consume = [&](int k) {
        const float4* sp = sbuf + (size_t)(k % STAGES) * ROW_F4;
        float4 v0 = sp[t];
        float4 v1 = sp[t + NTHREADS];

        float rs = sum4(v0) + sum4(v1);

        A.ac0x += v0.x; A.ac0y += v0.y; A.ac0z += v0.z; A.ac0w += v0.w;
        A.ac1x += v1.x; A.ac1y += v1.y; A.ac1z += v1.z; A.ac1w += v1.w;

        clog4(v0, A.cl0);
        clog4(v1, A.cl1);

        #pragma unroll
        for (int off = 16; off > 0; off >>= 1)
            rs += __shfl_down_sync(0xffffffffu, rs, off);
        if ((t & 31) == 0)
            atomicAdd(&g_rowsum[b + k * NBLOCKS], rs);
    };

    // ---- prologue: fill stages 0..STAGES-2 (cnt >= 55 > STAGES always) ----
    #pragma unroll
    for (int s = 0; s < STAGES - 1; ++s)
        issue(s);

    // ---- main loop: issue stage k+S-1, wait so group k is complete, consume ----
    int k = 0;
    for (; k + (STAGES - 1) < cnt; ++k) {
        issue(k + STAGES - 1);
        cp_wait<STAGES - 1>();
        consume(k);
    }

    // ---- tail: exactly STAGES-1 = 5 rows remain; descending wait counts ----
    cp_wait<4>(); consume(k); ++k;
    cp_wait<3>(); consume(k); ++k;
    cp_wait<2>(); consume(k); ++k;
    cp_wait<1>(); consume(k); ++k;
    cp_wait<0>(); consume(k); ++k;

    // ---- flush column accumulators ----
    int cA = 4 * t;
    atomicAdd(&g_colsum[cA + 0], A.ac0x);
    atomicAdd(&g_colsum[cA + 1], A.ac0y);
    atomicAdd(&g_colsum[cA + 2], A.ac0z);
    atomicAdd(&g_colsum[cA + 3], A.ac0w);
    int cB = 4096 + 4 * t;
    atomicAdd(&g_colsum[cB + 0], A.ac1x);
    atomicAdd(&g_colsum[cB + 1], A.ac1y);
    atomicAdd(&g_colsum[cB + 2], A.ac1z);
    atomicAdd(&g_colsum[cB + 3], A.ac1w);

    // ---- clogc cross-thread reduction in double ----
    double d = (double)(A.cl0 + A.cl1);
    #pragma unroll
    for (int off = 16; off > 0; off >>= 1)
        d += __shfl_down_sync(0xffffffffu, d, off);
    if ((t & 31) == 0)
        atomicAdd(&g_clogc, d);

    // ---- fused finalization: last block reduces the marginals ----
    __shared__ unsigned int s_islast;
    __threadfence();
    __syncthreads();
    if (t == 0)
        s_islast = (atomicAdd(&g_done, 1u) == (unsigned)(gridDim.x - 1));
    __syncthreads();
    if (!s_islast) return;

    double local = 0.0;
    for (int i = t; i < NROWS; i += NTHREADS) {
        float mx = g_rowsum[i];
        if (mx > 0.f) local += (double)mx * (double)__log2f(mx);
    }
    for (int j = t; j < MCOLS; j += NTHREADS) {
        float my = g_colsum[j];
        if (my > 0.f) local += (double)my * (double)__log2f(my);
    }

    __shared__ double sh[NTHREADS / 32];
    #pragma unroll
    for (int off = 16; off > 0; off >>= 1)
        local += __shfl_down_sync(0xffffffffu, local, off);
    if ((t & 31) == 0) sh[t >> 5] = local;
    __syncthreads();
    if (t < 32) {
        double v = (t < (NTHREADS / 32)) ? sh[t] : 0.0;
        #pragma unroll
        for (int off = 16; off > 0; off >>= 1)
            v += __shfl_down_sync(0xffffffffu, v, off);
        if (t == 0)
            out[0] = (float)(g_clogc - v);
    }
}

extern "C" void kernel_launch(void* const* d_in, const int* in_sizes, int n_in,
                              void* d_out, int out_size) {
    const float* C = (const float*)d_in[0];
    float* out = (float*)d_out;

    cudaFuncSetAttribute(mi_main_kernel,
                         cudaFuncAttributeMaxDynamicSharedMemorySize, SMEM_BYTES);

    mi_zero_kernel<<<32, 512>>>();
    mi_main_kernel<<<NBLOCKS, NTHREADS, SMEM_BYTES>>>(C, out);
}